// round 16
// baseline (speedup 1.0000x reference)
#include <cuda_runtime.h>
#include <cstdint>

#define IN_DIM   5000
#define ROW_B    (IN_DIM * 4)            // 20000 bytes per row
#define TOPK     50
#define BATCH    16384
#define H1       32
#define H2       16
#define OUT_DIM  30

#define NBIN     4096
#define MAXCAND  512

#define MLP_BLK   128                    // 4 warps
#define RW        4                      // rows per warp (double-buffered)
#define MLP_GRID  (BATCH / (4 * RW))     // 1024 CTAs

#define MAXL      52                     // max distinct lines per row (pad)
#define LINEF     32                     // floats per 128B line

// ---- dynamic smem layout (word offsets) ----
#define XBUF_OFF   0                                   // [4 warps][2][MAXL*32] floats
#define XBUF_WARP  (2 * MAXL * LINEF)                  // 3328
#define W1_OFF     (4 * XBUF_WARP)                     // 13312
#define W2_OFF     (W1_OFF + TOPK * H1)                // +1600
#define W3_OFF     (W2_OFF + H1 * H2)                  // +512
#define B1_OFF     (W3_OFF + H2 * OUT_DIM)             // +480
#define B2_OFF     (B1_OFF + H1)
#define B3_OFF     (B2_OFF + H2)
#define SIDX_OFF   (B3_OFF + 32)                       // ints
#define LOFF_OFF   (SIDX_OFF + 64)                     // int [4][MAXL]
#define GADR_OFF   (LOFF_OFF + 4 * MAXL)               // int [4][MAXL]
#define NL_OFF     (GADR_OFF + 4 * MAXL)               // int [4]
#define SMEM_WORDS (NL_OFF + 8)
#define SMEM_BYTES (SMEM_WORDS * 4)                    // ~66 KB

// scratch (no allocations allowed)
__device__ int g_topk_idx[64];

static __device__ __forceinline__ unsigned key32(float f) {
    unsigned u = __float_as_uint(f);
    return (u & 0x80000000u) ? ~u : (u | 0x80000000u);  // monotonic
}

// ---------------------------------------------------------------------------
// Kernel 1: single-CTA histogram top-k -> mask + compact index list (R13)
// ---------------------------------------------------------------------------
__global__ void __launch_bounds__(1024, 1)
k_topk(const float* __restrict__ logits, float* __restrict__ mask_out) {
    __shared__ int hist[NBIN];
    __shared__ int groupsum[128];
    __shared__ int sgrp[128];
    __shared__ int sbin[32];
    __shared__ int s_g, s_above, s_T, s_m, s_ncand;
    __shared__ int      cand_idx[MAXCAND];
    __shared__ unsigned cand_key[MAXCAND];
    __shared__ unsigned char sel[IN_DIM];
    __shared__ int wcnt[32], wbase[32];

    const int tid = threadIdx.x;
    const int w = tid >> 5, l = tid & 31;

    for (int i = tid; i < NBIN; i += 1024) hist[i] = 0;
    if (tid == 0) s_ncand = 0;
    __syncthreads();

    unsigned myu[5];
#pragma unroll
    for (int c = 0; c < 5; c++) {
        const int i = tid + c * 1024;
        if (i < IN_DIM) {
            const unsigned u = key32(logits[i]);
            myu[c] = u;
            atomicAdd(&hist[u >> 20], 1);
        } else myu[c] = 0u;
    }
    __syncthreads();

    if (tid < 128) {
        int s = 0;
#pragma unroll
        for (int j = 0; j < 32; j++) s += hist[tid * 32 + j];
        groupsum[tid] = s;
    }
    __syncthreads();
    if (tid < 128) {
        int s = 0;
        for (int g = tid; g < 128; g++) s += groupsum[g];
        sgrp[tid] = s;
    }
    __syncthreads();
    if (tid < 128) {
        const int nxt = (tid == 127) ? 0 : sgrp[tid + 1];
        if (sgrp[tid] >= TOPK && nxt < TOPK) { s_g = tid; s_above = nxt; }
    }
    __syncthreads();
    if (tid < 32) {
        const int b0 = s_g * 32;
        int s = 0;
        for (int b = b0 + tid; b < b0 + 32; b++) s += hist[b];
        sbin[tid] = s;
    }
    __syncthreads();
    if (tid < 32) {
        const int cur = sbin[tid] + s_above;
        const int nxt = (tid == 31) ? s_above : (sbin[tid + 1] + s_above);
        if (cur >= TOPK && nxt < TOPK) { s_T = s_g * 32 + tid; s_m = TOPK - nxt; }
    }
    __syncthreads();
    const int T = s_T, m = s_m;

#pragma unroll
    for (int c = 0; c < 5; c++) {
        const int i = tid + c * 1024;
        if (i < IN_DIM) {
            const int b = (int)(myu[c] >> 20);
            sel[i] = (b > T) ? 1 : 0;
            if (b == T) {
                int cc = atomicAdd(&s_ncand, 1);
                if (cc < MAXCAND) { cand_idx[cc] = i; cand_key[cc] = myu[c]; }
            }
        }
    }
    __syncthreads();

    const int nc = min(s_ncand, MAXCAND);
    for (int ci = tid; ci < nc; ci += 1024) {
        const unsigned ki = cand_key[ci];
        const int      ii = cand_idx[ci];
        int rank = 0;
        for (int cj = 0; cj < nc; cj++) {
            const unsigned kj = cand_key[cj];
            rank += (kj > ki || (kj == ki && cand_idx[cj] < ii)) ? 1 : 0;
        }
        if (rank < m) sel[ii] = 1;
    }
    __syncthreads();

    if (mask_out) {
#pragma unroll
        for (int c = 0; c < 5; c++) {
            const int i = tid + c * 1024;
            if (i < IN_DIM) mask_out[i] = sel[i] ? 1.0f : 0.0f;
        }
    }

    unsigned bm[5];
    int cnt = 0;
#pragma unroll
    for (int c = 0; c < 5; c++) {
        const int i = w * 160 + c * 32 + l;
        const bool s = (i < IN_DIM) && sel[i];
        bm[c] = __ballot_sync(0xffffffffu, s);
        cnt += __popc(bm[c]);
    }
    if (l == 0) wcnt[w] = cnt;
    __syncthreads();
    if (tid < 32) {
        int v = wcnt[tid];
        int inc = v;
#pragma unroll
        for (int d = 1; d < 32; d <<= 1) {
            int t = __shfl_up_sync(0xffffffffu, inc, d);
            if (tid >= d) inc += t;
        }
        wbase[tid] = inc - v;
    }
    __syncthreads();
    int base = wbase[w];
#pragma unroll
    for (int c = 0; c < 5; c++) {
        const int i = w * 160 + c * 32 + l;
        const unsigned b = bm[c];
        if ((i < IN_DIM) && sel[i])
            g_topk_idx[base + __popc(b & ((1u << l) - 1u))] = i;
        base += __popc(b);
    }
}

// ---------------------------------------------------------------------------
// Kernel 2: DEDUPED FULL-LINE gather via cp.async -> smem, then MLP.
//   Row stride 20000 = 32 (mod 128) -> 4 line-alignment classes (row & 3).
//   Per class: deduped relative line-offset list + per-k smem gather address,
//   precomputed once per CTA. Each warp double-buffers RW rows: fetch row i+1
//   (<=13 cp.async.cg x 512B = up to 52 lines) while computing row i.
// ---------------------------------------------------------------------------
__global__ void __launch_bounds__(MLP_BLK, 3)
k_mlp(const float* __restrict__ x,
      const float* __restrict__ W1, const float* __restrict__ b1,
      const float* __restrict__ W2, const float* __restrict__ b2,
      const float* __restrict__ W3, const float* __restrict__ b3,
      float* __restrict__ out) {
    extern __shared__ float sm[];
    int*  sidx  = (int*)(sm + SIDX_OFF);
    int*  loff  = (int*)(sm + LOFF_OFF);   // [4][MAXL] relative byte offsets
    int*  gadr  = (int*)(sm + GADR_OFF);   // [4][MAXL] per-k smem float index
    int*  nlin  = (int*)(sm + NL_OFF);

    const int tid  = threadIdx.x;
    const int warp = tid >> 5;
    const int lane = tid & 31;

    // ---- topk-independent weight staging overlaps k_topk (PDL) ----
    for (int t = tid; t < H1 * H2; t += MLP_BLK)      sm[W2_OFF + t] = W2[t];
    for (int t = tid; t < H2 * OUT_DIM; t += MLP_BLK) sm[W3_OFF + t] = W3[t];
    if (tid < H1)      sm[B1_OFF + tid] = b1[tid];
    if (tid < H2)      sm[B2_OFF + tid] = b2[tid];
    if (tid < OUT_DIM) sm[B3_OFF + tid] = b3[tid];

#if __CUDA_ARCH__ >= 900
    cudaGridDependencySynchronize();
#endif

    if (tid < TOPK) sidx[tid] = g_topk_idx[tid];
    __syncthreads();

    // W1 gather (topk-dependent)
    for (int t = tid; t < TOPK * H1; t += MLP_BLK)
        sm[W1_OFF + t] = W1[(long)sidx[t >> 5] * H1 + (t & 31)];

    // per-class line tables: thread a in [0,4) scans sorted columns
    if (tid < 4) {
        const int a = tid;
        int n = 0, prev = -1;
        for (int k = 0; k < TOPK; k++) {
            const int b  = 32 * a + 4 * sidx[k];
            const int ls = b & ~127;
            if (ls != prev) { loff[a * MAXL + n] = ls - 32 * a; prev = ls; n++; }
            gadr[a * MAXL + k] = (n - 1) * LINEF + ((b & 127) >> 2);
        }
        nlin[a] = n;
    }
    __syncthreads();

    const int row0 = (blockIdx.x * 4 + warp) * RW;
    float* xbuf0 = sm + XBUF_OFF + warp * XBUF_WARP;
    float* xbuf1 = xbuf0 + MAXL * LINEF;

    const int myline  = lane >> 3;          // 0..3 within each 4-line pass
    const int mychunk = (lane & 7) * 16;    // byte offset within line

    // fetch row -> buf (warp-collective, <=13 passes of 4 lines)
    auto fetch = [&](int row, float* buf) {
        const int a  = row & 3;
        const int nl = nlin[a];
        const char* rowp = (const char*)x + (long)row * ROW_B;
        const int* lo = loff + a * MAXL;
#pragma unroll
        for (int p = 0; p < 13; p++) {
            const int line = p * 4 + myline;
            if (line < nl) {
                const char* src = rowp + lo[line] + mychunk;
                const unsigned dst = (unsigned)__cvta_generic_to_shared(
                    (char*)buf + line * 128 + mychunk);
                asm volatile("cp.async.cg.shared.global [%0], [%1], 16;"
                             :: "r"(dst), "l"(src));
            }
        }
        asm volatile("cp.async.commit_group;");
    };

    // compute row from buf
    auto compute = [&](int row, const float* buf) {
        const int a = row & 3;
        const int* ga = gadr + a * MAXL;

        float p = sm[B1_OFF + lane];
#pragma unroll
        for (int k = 0; k < TOPK; k++) {
            const float v = buf[ga[k]];                    // broadcast LDS
            p = fmaf(v, sm[W1_OFF + k * H1 + lane], p);
        }
        const float a1 = fmaxf(p, 0.0f);

        const int j2 = lane & 15;
        float s2 = sm[B2_OFF + j2];
#pragma unroll
        for (int i = 0; i < H1; i++) {
            const float v = __shfl_sync(0xffffffffu, a1, i);
            s2 = fmaf(v, sm[W2_OFF + i * H2 + j2], s2);
        }
        const float a2 = fmaxf(s2, 0.0f);

        float o = (lane < OUT_DIM) ? sm[B3_OFF + lane] : 0.0f;
#pragma unroll
        for (int i = 0; i < H2; i++) {
            const float v = __shfl_sync(0xffffffffu, a2, i);
            if (lane < OUT_DIM)
                o = fmaf(v, sm[W3_OFF + i * OUT_DIM + lane], o);
        }
        if (lane < OUT_DIM)
            out[(long)row * OUT_DIM + lane] = o;
    };

    // double-buffered pipeline: fetch i+1 while computing i
    fetch(row0, xbuf0);
#pragma unroll
    for (int i = 0; i < RW; i++) {
        if (i + 1 < RW) {
            fetch(row0 + i + 1, (i & 1) ? xbuf0 : xbuf1);
            asm volatile("cp.async.wait_group 1;");
        } else {
            asm volatile("cp.async.wait_group 0;");
        }
        __syncwarp();
        compute(row0 + i, (i & 1) ? xbuf1 : xbuf0);
        __syncwarp();
    }
}

// ---------------------------------------------------------------------------
extern "C" void kernel_launch(void* const* d_in, const int* in_sizes, int n_in,
                              void* d_out, int out_size) {
    const float* x      = (const float*)d_in[0];
    const float* logits = (const float*)d_in[1];
    const float* W1     = (const float*)d_in[2];
    const float* b1     = (const float*)d_in[3];
    const float* W2     = (const float*)d_in[4];
    const float* b2     = (const float*)d_in[5];
    const float* W3     = (const float*)d_in[6];
    const float* b3     = (const float*)d_in[7];

    float* out  = (float*)d_out;
    float* mask = nullptr;
    if (out_size >= BATCH * OUT_DIM + IN_DIM)
        mask = out + (long)BATCH * OUT_DIM;   // tuple order: (out, mask)

    cudaFuncSetAttribute(k_mlp, cudaFuncAttributeMaxDynamicSharedMemorySize,
                         SMEM_BYTES);   // idempotent, every call

    k_topk<<<1, 1024>>>(logits, mask);

    // PDL launch: k_mlp overlaps k_topk; syncs before reading g_topk_idx.
    cudaLaunchConfig_t cfg = {};
    cfg.gridDim  = dim3(MLP_GRID);
    cfg.blockDim = dim3(MLP_BLK);
    cfg.dynamicSmemBytes = SMEM_BYTES;
    cfg.stream = 0;
    cudaLaunchAttribute attrs[1];
    attrs[0].id = cudaLaunchAttributeProgrammaticStreamSerialization;
    attrs[0].val.programmaticStreamSerializationAllowed = 1;
    cfg.attrs = attrs;
    cfg.numAttrs = 1;
    cudaError_t err = cudaLaunchKernelEx(&cfg, k_mlp, x, W1, b1, W2, b2, W3, b3, out);
    if (err != cudaSuccess) {
        k_mlp<<<MLP_GRID, MLP_BLK, SMEM_BYTES>>>(x, W1, b1, W2, b2, W3, b3, out);
    }
}